// round 2
// baseline (speedup 1.0000x reference)
#include <cuda_runtime.h>
#include <stdint.h>
#include <math.h>

#define BATCH 2
#define SEQ   8192
#define DIM   1024
#define HEADS 8
#define DH    64
#define HDH   512
#define WIN   64
#define NW    (SEQ/WIN)
#define NQ    1024
#define NKV   2048
#define NROWS (BATCH*SEQ)

// ---------------- scratch (static device allocations; no cudaMalloc) -------
__device__ float g_xn  [NROWS*DIM];          // layernormed x
__device__ float g_qkv [NROWS*3*HDH];        // light qkv
__device__ float g_lo  [NROWS*HDH];          // light attention out (pre w_out)
__device__ float g_s   [2][NROWS];           // routing logits (0=q,1=kv)
__device__ float g_a   [2][BATCH];           // coor-descent fixed points
__device__ int   g_sel [2][BATCH][NKV];      // selected indices (q uses NQ)
__device__ float g_xqn [BATCH*NQ*DIM];       // gathered+rmsnormed xq
__device__ float g_xkvn[BATCH*NKV*DIM];      // gathered+rmsnormed xkv
__device__ float g_qh  [BATCH*NQ*HDH];       // heavy q
__device__ float g_kvh [BATCH*NKV*2*HDH];    // heavy kv (per head: k64|v64)
__device__ float g_oh  [BATCH*NQ*HDH];       // heavy attn out
__device__ float g_ro  [BATCH*NQ*DIM];       // routed_out

// ---------------- reductions ----------------
__device__ __forceinline__ float blockSum(float v){
    __shared__ float sh[33];
    int lane = threadIdx.x & 31, wid = threadIdx.x >> 5;
    #pragma unroll
    for (int o=16;o>0;o>>=1) v += __shfl_down_sync(0xffffffffu, v, o);
    __syncthreads();
    if (lane==0) sh[wid]=v;
    __syncthreads();
    if (wid==0){
        float r = (lane < (blockDim.x>>5)) ? sh[lane] : 0.f;
        #pragma unroll
        for (int o=16;o>0;o>>=1) r += __shfl_down_sync(0xffffffffu, r, o);
        if (lane==0) sh[32]=r;
    }
    __syncthreads();
    return sh[32];
}

__device__ __forceinline__ double blockSumD(double v){
    __shared__ double shd[33];
    int lane = threadIdx.x & 31, wid = threadIdx.x >> 5;
    #pragma unroll
    for (int o=16;o>0;o>>=1) v += __shfl_down_sync(0xffffffffu, v, o);
    __syncthreads();
    if (lane==0) shd[wid]=v;
    __syncthreads();
    if (wid==0){
        double r = (lane < (blockDim.x>>5)) ? shd[lane] : 0.0;
        #pragma unroll
        for (int o=16;o>0;o>>=1) r += __shfl_down_sync(0xffffffffu, r, o);
        if (lane==0) shd[32]=r;
    }
    __syncthreads();
    return shd[32];
}

// ---------------- fused layernorm + routing logits ----------------
__global__ __launch_bounds__(256) void k_pre(const float* __restrict__ x,
                                             const float* __restrict__ ln_g,
                                             const float* __restrict__ ln_b,
                                             const float* __restrict__ rt_q,
                                             const float* __restrict__ rt_kv){
    __shared__ float xr[DIM];
    size_t row = blockIdx.x;
    const float* xp = x + row*DIM;
    float s=0.f, s2=0.f, dq=0.f, dk=0.f;
    for (int d=threadIdx.x; d<DIM; d+=256){
        float v = xp[d]; xr[d]=v;
        s += v; s2 += v*v; dq += v*rt_q[d]; dk += v*rt_kv[d];
    }
    s  = blockSum(s);
    s2 = blockSum(s2);
    dq = blockSum(dq);
    dk = blockSum(dk);
    if (threadIdx.x==0){ g_s[0][row]=dq; g_s[1][row]=dk; }
    float m    = s * (1.f/DIM);
    float var  = s2 * (1.f/DIM) - m*m;
    float rstd = rsqrtf(var + 1e-5f);
    for (int d=threadIdx.x; d<DIM; d+=256)
        g_xn[row*DIM+d] = (xr[d]-m)*rstd*ln_g[d] + ln_b[d];
}

// ---------------- SGEMM 128x128x8, 8x8/thread. All dims divide evenly. ----
__global__ __launch_bounds__(256) void sgemm128(int M,int N,int K,
                                                const float* __restrict__ A,
                                                const float* __restrict__ B,
                                                float* __restrict__ C,
                                                const float* __restrict__ bias){
    __shared__ float As[8][128];
    __shared__ float Bs[8][128];
    const int tid  = threadIdx.x;
    const int tcol = tid & 15;
    const int trow = tid >> 4;
    const size_t bx = blockIdx.x, by = blockIdx.y;
    const float* Ap = A + by*128*(size_t)K;
    const float* Bp = B + bx*128;
    const int arow = tid >> 1;
    const int acol = (tid & 1)*4;
    const int brw  = tid >> 5;
    const int bcl  = (tid & 31)*4;
    float acc[8][8];
    #pragma unroll
    for (int i=0;i<8;i++)
        #pragma unroll
        for (int j=0;j<8;j++) acc[i][j]=0.f;
    for (int k0=0;k0<K;k0+=8){
        float4 av = *(const float4*)(Ap + (size_t)arow*K + acol);
        As[acol+0][arow]=av.x; As[acol+1][arow]=av.y;
        As[acol+2][arow]=av.z; As[acol+3][arow]=av.w;
        *(float4*)(&Bs[brw][bcl]) = *(const float4*)(Bp + (size_t)brw*N + bcl);
        __syncthreads();
        Ap += 8; Bp += (size_t)8*N;
        #pragma unroll
        for (int kk=0;kk<8;kk++){
            float rm[8], rn[8];
            #pragma unroll
            for (int i=0;i<8;i++) rm[i]=As[kk][trow*8+i];
            #pragma unroll
            for (int j=0;j<8;j++) rn[j]=Bs[kk][tcol*8+j];
            #pragma unroll
            for (int i=0;i<8;i++)
                #pragma unroll
                for (int j=0;j<8;j++) acc[i][j] += rm[i]*rn[j];
        }
        __syncthreads();
    }
    float bb[8];
    #pragma unroll
    for (int j=0;j<8;j++) bb[j] = bias ? bias[bx*128 + tcol*8 + j] : 0.f;
    float* Cp = C + (by*128 + trow*8)*(size_t)N + bx*128 + tcol*8;
    #pragma unroll
    for (int i=0;i<8;i++){
        float4 v0 = make_float4(acc[i][0]+bb[0], acc[i][1]+bb[1],
                                acc[i][2]+bb[2], acc[i][3]+bb[3]);
        float4 v1 = make_float4(acc[i][4]+bb[4], acc[i][5]+bb[5],
                                acc[i][6]+bb[6], acc[i][7]+bb[7]);
        *(float4*)(Cp + (size_t)i*N)     = v0;
        *(float4*)(Cp + (size_t)i*N + 4) = v1;
    }
}

// ---------------- light (windowed) attention ----------------
__global__ __launch_bounds__(64) void k_light(){
    const int w = blockIdx.x, h = blockIdx.y, b = blockIdx.z, t = threadIdx.x;
    __shared__ float ks[WIN][DH];
    __shared__ float vs[WIN][DH];
    const int n0 = w*WIN;
    const float* qp = g_qkv + ((size_t)(b*SEQ + n0 + t))*(3*HDH) + h*DH;
    float q[DH];
    #pragma unroll
    for (int d4=0; d4<DH; d4+=4){
        float4 v = *(const float4*)(qp + d4);
        q[d4]=v.x*0.125f; q[d4+1]=v.y*0.125f; q[d4+2]=v.z*0.125f; q[d4+3]=v.w*0.125f;
    }
    float m=-1e30f, l=0.f, o[DH];
    #pragma unroll
    for (int d=0; d<DH; d++) o[d]=0.f;
    for (int c=0;c<3;c++){
        const int wc = w-1+c;
        if (wc<0 || wc>=NW) continue;   // uniform branch across block
        __syncthreads();
        const float* kb = g_qkv + ((size_t)(b*SEQ + wc*WIN))*(3*HDH) + HDH + h*DH;
        #pragma unroll 4
        for (int i=0;i<WIN;i++){
            ks[i][t] = kb[(size_t)i*(3*HDH) + t];
            vs[i][t] = kb[(size_t)i*(3*HDH) + HDH + t];
        }
        __syncthreads();
        for (int j=0;j<WIN;j++){
            float xv=0.f;
            #pragma unroll
            for (int d=0;d<DH;d++) xv += q[d]*ks[j][d];
            float mn = fmaxf(m, xv);
            float f  = __expf(m-mn);
            float e  = __expf(xv-mn);
            l = l*f + e;
            #pragma unroll
            for (int d=0;d<DH;d++) o[d] = o[d]*f + e*vs[j][d];
            m = mn;
        }
    }
    float inv = 1.f/l;
    float* op = g_lo + ((size_t)(b*SEQ + n0 + t))*HDH + h*DH;
    #pragma unroll
    for (int d4=0; d4<DH; d4+=4){
        float4 v = make_float4(o[d4]*inv, o[d4+1]*inv, o[d4+2]*inv, o[d4+3]*inv);
        *(float4*)(op + d4) = v;
    }
}

// ---------------- coor-descent scalar fixed point ----------------
__global__ __launch_bounds__(1024) void k_coor(){
    const int b = blockIdx.x, r = blockIdx.y;
    const float* s = g_s[r] + (size_t)b*SEQ;
    float sv[8];
    #pragma unroll
    for (int i=0;i<8;i++) sv[i] = s[threadIdx.x + i*1024];
    const double logk = (double)logf(r==0 ? 1152.0f : 2304.0f);
    double a = logk - (double)logf(8192.0f);   // iteration 1 (b = -s -> LSE(0)=log N)
    for (int it=0; it<49; it++){               // iterations 2..50
        double tt=0.0;
        #pragma unroll
        for (int i=0;i<8;i++) tt += exp(fmin((double)sv[i], -a));
        tt = blockSumD(tt);
        a = logk - log(tt);
    }
    if (threadIdx.x==0) g_a[r][b] = (float)a;
}

// ---------------- top-k selection (exact JAX tie semantics via sort) -------
__global__ __launch_bounds__(1024) void k_select(){
    extern __shared__ unsigned long long keys[];
    const int b = blockIdx.x, r = blockIdx.y;
    const float a = g_a[r][b];
    const float* s = g_s[r] + (size_t)b*SEQ;
    for (int i=threadIdx.x; i<SEQ; i+=1024){
        float sc = expf(fminf(s[i]+a, 0.f));   // score in (0,1], plateau at 1.0
        unsigned long long key = ((unsigned long long)__float_as_uint(sc)<<32)
                               | (unsigned int)(SEQ-1-i);   // ties: lowest idx wins
        keys[i] = ~key;                         // ascending sort of ~key == key desc
    }
    __syncthreads();
    for (int k=2;k<=SEQ;k<<=1){
        for (int j=k>>1;j>0;j>>=1){
            for (int i=threadIdx.x;i<SEQ;i+=1024){
                int ixj = i ^ j;
                if (ixj > i){
                    unsigned long long va = keys[i], vb = keys[ixj];
                    bool sw = ((i & k)==0) ? (va > vb) : (va < vb);
                    if (sw){ keys[i]=vb; keys[ixj]=va; }
                }
            }
            __syncthreads();
        }
    }
    const int cnt = (r==0) ? NQ : NKV;
    for (int i=threadIdx.x;i<cnt;i+=1024){
        unsigned long long key = ~keys[i];
        g_sel[r][b][i] = (SEQ-1) - (int)(key & 0xffffffffu);
    }
}

// ---------------- gather + rmsnorm ----------------
__global__ __launch_bounds__(256) void k_gather(const float* __restrict__ x,
                                                const float* __restrict__ rms_g,
                                                int route){
    const int j = blockIdx.x, b = blockIdx.y;
    const int cnt = route ? NKV : NQ;
    float* out = route ? g_xkvn : g_xqn;
    const int n = g_sel[route][b][j];
    const float* xp = x + ((size_t)(b*SEQ) + n)*DIM;
    float ss=0.f;
    for (int d=threadIdx.x; d<DIM; d+=256){ float v=xp[d]; ss += v*v; }
    ss = blockSum(ss);
    const float sc = 32.f / fmaxf(sqrtf(ss), 1e-12f);   // sqrt(DIM)=32
    float* op = out + ((size_t)b*cnt + j)*DIM;
    for (int d=threadIdx.x; d<DIM; d+=256) op[d] = xp[d]*sc*rms_g[d];
}

// ---------------- heavy attention (null key + 2048 routed keys) -----------
__global__ __launch_bounds__(64) void k_heavy(const float* __restrict__ null_kv){
    const int qc=blockIdx.x, h=blockIdx.y, b=blockIdx.z, t=threadIdx.x;
    __shared__ float ks[64][DH];
    __shared__ float vs[64][DH];
    const float* qp = g_qh + ((size_t)(b*NQ + qc*64 + t))*HDH + h*DH;
    float q[DH];
    #pragma unroll
    for (int d4=0; d4<DH; d4+=4){
        float4 v = *(const float4*)(qp + d4);
        q[d4]=v.x*0.125f; q[d4+1]=v.y*0.125f; q[d4+2]=v.z*0.125f; q[d4+3]=v.w*0.125f;
    }
    const float* nk = null_kv + h*DH;
    const float* nv = null_kv + HDH + h*DH;
    float x0=0.f;
    #pragma unroll
    for (int d=0;d<DH;d++) x0 += q[d]*nk[d];
    float m=x0, l=1.f, o[DH];
    #pragma unroll
    for (int d=0;d<DH;d++) o[d]=nv[d];
    for (int kc=0;kc<NKV/64;kc++){
        __syncthreads();
        const float* kb = g_kvh + ((size_t)(b*NKV + kc*64))*(2*HDH) + h*(2*DH);
        #pragma unroll 4
        for (int i=0;i<64;i++){
            ks[i][t] = kb[(size_t)i*(2*HDH) + t];
            vs[i][t] = kb[(size_t)i*(2*HDH) + DH + t];
        }
        __syncthreads();
        for (int j=0;j<64;j++){
            float xv=0.f;
            #pragma unroll
            for (int d=0;d<DH;d++) xv += q[d]*ks[j][d];
            float mn = fmaxf(m, xv);
            float f  = __expf(m-mn);
            float e  = __expf(xv-mn);
            l = l*f + e;
            #pragma unroll
            for (int d=0;d<DH;d++) o[d] = o[d]*f + e*vs[j][d];
            m = mn;
        }
    }
    float inv = 1.f/l;
    float* op = g_oh + ((size_t)(b*NQ + qc*64 + t))*HDH + h*DH;
    #pragma unroll
    for (int d4=0; d4<DH; d4+=4){
        float4 v = make_float4(o[d4]*inv, o[d4+1]*inv, o[d4+2]*inv, o[d4+3]*inv);
        *(float4*)(op + d4) = v;
    }
}

// ---------------- scatter routed output ----------------
__global__ __launch_bounds__(256) void k_scatter(const float* __restrict__ null_q,
                                                 float* __restrict__ out){
    const int j=blockIdx.x, b=blockIdx.y;
    const int n = g_sel[0][b][j];
    float* op = out + ((size_t)(b*SEQ) + n)*DIM;
    const float* rp = g_ro + ((size_t)(b*NQ) + j)*DIM;
    for (int d=threadIdx.x; d<DIM; d+=256)
        op[d] += rp[d] - null_q[d];
}

// ---------------- launch ----------------
extern "C" void kernel_launch(void* const* d_in, const int* in_sizes, int n_in,
                              void* d_out, int out_size){
    (void)in_sizes; (void)n_in; (void)out_size;
    const float* x       = (const float*)d_in[0];
    const float* ln_g    = (const float*)d_in[1];
    const float* ln_b    = (const float*)d_in[2];
    const float* w_qkv_l = (const float*)d_in[3];
    const float* w_out_l = (const float*)d_in[4];
    const float* null_q  = (const float*)d_in[5];
    const float* rt_q    = (const float*)d_in[6];
    const float* rt_kv   = (const float*)d_in[7];
    const float* rms_g   = (const float*)d_in[8];
    const float* w_q_h   = (const float*)d_in[9];
    const float* w_kv_h  = (const float*)d_in[10];
    const float* null_kv = (const float*)d_in[11];
    const float* w_out_h = (const float*)d_in[12];
    float* out = (float*)d_out;

    float *p_xn,*p_qkv,*p_lo,*p_xqn,*p_xkvn,*p_qh,*p_kvh,*p_oh,*p_ro;
    cudaGetSymbolAddress((void**)&p_xn,   g_xn);
    cudaGetSymbolAddress((void**)&p_qkv,  g_qkv);
    cudaGetSymbolAddress((void**)&p_lo,   g_lo);
    cudaGetSymbolAddress((void**)&p_xqn,  g_xqn);
    cudaGetSymbolAddress((void**)&p_xkvn, g_xkvn);
    cudaGetSymbolAddress((void**)&p_qh,   g_qh);
    cudaGetSymbolAddress((void**)&p_kvh,  g_kvh);
    cudaGetSymbolAddress((void**)&p_oh,   g_oh);
    cudaGetSymbolAddress((void**)&p_ro,   g_ro);

    cudaFuncSetAttribute(k_select, cudaFuncAttributeMaxDynamicSharedMemorySize, 65536);

    // 1. layernorm + routing logits (one pass over x)
    k_pre<<<NROWS, 256>>>(x, ln_g, ln_b, rt_q, rt_kv);
    // 2. light qkv projection
    sgemm128<<<dim3(3*HDH/128, NROWS/128), 256>>>(NROWS, 3*HDH, DIM, p_xn, w_qkv_l, p_qkv, nullptr);
    // 3. routing fixed point + selection (independent of 2)
    k_coor<<<dim3(BATCH,2), 1024>>>();
    k_select<<<dim3(BATCH,2), 1024, 65536>>>();
    // 4. windowed light attention
    k_light<<<dim3(NW, HEADS, BATCH), 64>>>();
    // 5. light output projection, +null_q bias everywhere -> d_out
    sgemm128<<<dim3(DIM/128, NROWS/128), 256>>>(NROWS, DIM, HDH, p_lo, w_out_l, out, null_q);
    // 6. gather + rmsnorm routed tokens
    k_gather<<<dim3(NQ,  BATCH), 256>>>(x, rms_g, 0);
    k_gather<<<dim3(NKV, BATCH), 256>>>(x, rms_g, 1);
    // 7. heavy projections
    sgemm128<<<dim3(HDH/128,   BATCH*NQ/128),  256>>>(BATCH*NQ,  HDH,   DIM, p_xqn,  w_q_h,  p_qh,  nullptr);
    sgemm128<<<dim3(2*HDH/128, BATCH*NKV/128), 256>>>(BATCH*NKV, 2*HDH, DIM, p_xkvn, w_kv_h, p_kvh, nullptr);
    // 8. heavy attention (null kv prepended)
    k_heavy<<<dim3(NQ/64, HEADS, BATCH), 64>>>(null_kv);
    // 9. heavy output projection
    sgemm128<<<dim3(DIM/128, BATCH*NQ/128), 256>>>(BATCH*NQ, DIM, HDH, p_oh, w_out_h, p_ro, nullptr);
    // 10. scatter: out[sel] += routed - null_q
    k_scatter<<<dim3(NQ, BATCH), 256>>>(null_q, out);
}

// round 4
// speedup vs baseline: 1.7172x; 1.7172x over previous
#include <cuda_runtime.h>
#include <cuda_bf16.h>
#include <stdint.h>
#include <math.h>

#define BATCH 2
#define SEQ   8192
#define DIM   1024
#define HEADS 8
#define DH    64
#define HDH   512
#define WIN   64
#define NW    (SEQ/WIN)
#define NQ    1024
#define NKV   2048
#define NROWS (BATCH*SEQ)
#define NSPLIT 4
#define KV_PER_SPLIT (NKV/NSPLIT)

// ---------------- scratch ----------------
__device__ float g_xn  [NROWS*DIM];
__device__ float g_qkv [NROWS*3*HDH];
__device__ float g_lo  [NROWS*HDH];
__device__ float g_s   [2][NROWS];
__device__ float g_a   [2][BATCH];
__device__ int   g_sel [2][BATCH][NKV];
__device__ float g_xqn [BATCH*NQ*DIM];
__device__ float g_xkvn[BATCH*NKV*DIM];
__device__ float g_qh  [BATCH*NQ*HDH];
__device__ float g_kvh [BATCH*NKV*2*HDH];
__device__ float g_oh  [BATCH*NQ*HDH];
__device__ float g_ro  [BATCH*NQ*DIM];
__device__ float g_pm  [BATCH*HEADS*NSPLIT*NQ];
__device__ float g_pl  [BATCH*HEADS*NSPLIT*NQ];
__device__ float g_po  [(size_t)BATCH*HEADS*NSPLIT*NQ*DH];

// ---------------- reductions ----------------
__device__ __forceinline__ float blockSum(float v){
    __shared__ float sh[33];
    int lane = threadIdx.x & 31, wid = threadIdx.x >> 5;
    #pragma unroll
    for (int o=16;o>0;o>>=1) v += __shfl_down_sync(0xffffffffu, v, o);
    __syncthreads();
    if (lane==0) sh[wid]=v;
    __syncthreads();
    if (wid==0){
        float r = (lane < (blockDim.x>>5)) ? sh[lane] : 0.f;
        #pragma unroll
        for (int o=16;o>0;o>>=1) r += __shfl_down_sync(0xffffffffu, r, o);
        if (lane==0) sh[32]=r;
    }
    __syncthreads();
    return sh[32];
}

__device__ __forceinline__ double blockSumD(double v){
    __shared__ double shd[33];
    int lane = threadIdx.x & 31, wid = threadIdx.x >> 5;
    #pragma unroll
    for (int o=16;o>0;o>>=1) v += __shfl_down_sync(0xffffffffu, v, o);
    __syncthreads();
    if (lane==0) shd[wid]=v;
    __syncthreads();
    if (wid==0){
        double r = (lane < (blockDim.x>>5)) ? shd[lane] : 0.0;
        #pragma unroll
        for (int o=16;o>0;o>>=1) r += __shfl_down_sync(0xffffffffu, r, o);
        if (lane==0) shd[32]=r;
    }
    __syncthreads();
    return shd[32];
}

// ---------------- fused layernorm + routing logits ----------------
__global__ __launch_bounds__(256) void k_pre(const float* __restrict__ x,
                                             const float* __restrict__ ln_g,
                                             const float* __restrict__ ln_b,
                                             const float* __restrict__ rt_q,
                                             const float* __restrict__ rt_kv){
    __shared__ float xr[DIM];
    size_t row = blockIdx.x;
    const float* xp = x + row*DIM;
    float s=0.f, s2=0.f, dq=0.f, dk=0.f;
    for (int d=threadIdx.x; d<DIM; d+=256){
        float v = xp[d]; xr[d]=v;
        s += v; s2 += v*v; dq += v*rt_q[d]; dk += v*rt_kv[d];
    }
    s  = blockSum(s);
    s2 = blockSum(s2);
    dq = blockSum(dq);
    dk = blockSum(dk);
    if (threadIdx.x==0){ g_s[0][row]=dq; g_s[1][row]=dk; }
    float m    = s * (1.f/DIM);
    float var  = s2 * (1.f/DIM) - m*m;
    float rstd = rsqrtf(var + 1e-5f);
    for (int d=threadIdx.x; d<DIM; d+=256)
        g_xn[row*DIM+d] = (xr[d]-m)*rstd*ln_g[d] + ln_b[d];
}

// ================= tensor-core GEMM (bf16x2 split, fp32-accurate) =========
// C[M,N] = A[M,K] * B[K,N] (+bias[N]).  M,N mult of 128, K mult of 16.
__device__ __forceinline__ void split2(float x, float y, uint32_t& hi, uint32_t& lo){
    __nv_bfloat16 hx = __float2bfloat16_rn(x), hy = __float2bfloat16_rn(y);
    float rx = x - __bfloat162float(hx);
    float ry = y - __bfloat162float(hy);
    __nv_bfloat16 lx = __float2bfloat16_rn(rx), ly = __float2bfloat16_rn(ry);
    hi = (uint32_t)__bfloat16_as_ushort(hx) | ((uint32_t)__bfloat16_as_ushort(hy)<<16);
    lo = (uint32_t)__bfloat16_as_ushort(lx) | ((uint32_t)__bfloat16_as_ushort(ly)<<16);
}

#define LDM_X4(r0,r1,r2,r3,p) \
    asm volatile("ldmatrix.sync.aligned.m8n8.x4.shared.b16 {%0,%1,%2,%3},[%4];" \
        : "=r"(r0),"=r"(r1),"=r"(r2),"=r"(r3) : "r"(p))
#define LDM_X2T(r0,r1,p) \
    asm volatile("ldmatrix.sync.aligned.m8n8.x2.trans.shared.b16 {%0,%1},[%2];" \
        : "=r"(r0),"=r"(r1) : "r"(p))
#define MMA16816(d,a0,a1,a2,a3,b0,b1) \
    asm volatile("mma.sync.aligned.m16n8k16.row.col.f32.bf16.bf16.f32 " \
        "{%0,%1,%2,%3},{%4,%5,%6,%7},{%8,%9},{%0,%1,%2,%3};" \
        : "+f"(d[0]),"+f"(d[1]),"+f"(d[2]),"+f"(d[3]) \
        : "r"(a0),"r"(a1),"r"(a2),"r"(a3),"r"(b0),"r"(b1))

#define A_LD 24
#define B_LD 136

__global__ __launch_bounds__(256,2) void gemm_tc(int M,int N,int K,
                                                 const float* __restrict__ A,
                                                 const float* __restrict__ B,
                                                 float* __restrict__ C,
                                                 const float* __restrict__ bias){
    __shared__ __nv_bfloat16 Ah[2][128][A_LD];
    __shared__ __nv_bfloat16 Al[2][128][A_LD];
    __shared__ __nv_bfloat16 Bh[2][16][B_LD];
    __shared__ __nv_bfloat16 Bl[2][16][B_LD];
    const int tid  = threadIdx.x;
    const int lane = tid & 31, wid = tid >> 5;
    const int wm = (wid>>2)*64;      // warp m-base (0 or 64)
    const int wn = (wid&3)*32;       // warp n-base (0,32,64,96)
    const size_t bx = blockIdx.x, by = blockIdx.y;
    const float* Ag = A + by*128*(size_t)K;
    const float* Bg = B + bx*128;
    // global-load assignments
    const int ar = tid>>1, ac = (tid&1)*8;     // A: 128 rows x 16 cols, 8 floats/thread
    const int br = tid>>4, bc = (tid&15)*8;    // B: 16 rows x 128 cols, 8 floats/thread
    // ldmatrix lane addressing
    const int arow  = (lane&7) + ((lane>>3)&1)*8;
    const int acolb = (lane>>4)*8;
    const int bkrow = lane & 15;

    float acc[4][4][4];
    #pragma unroll
    for (int i=0;i<4;i++)
        #pragma unroll
        for (int j=0;j<4;j++)
            #pragma unroll
            for (int c=0;c<4;c++) acc[i][j][c]=0.f;

    const int nk = K >> 4;
    float4 pa0,pa1,pb0,pb1;
    {   // prefetch tile 0
        const float* Ap = Ag + (size_t)ar*K + ac;
        pa0 = *(const float4*)Ap; pa1 = *(const float4*)(Ap+4);
        const float* Bp = Bg + (size_t)br*N + bc;
        pb0 = *(const float4*)Bp; pb1 = *(const float4*)(Bp+4);
    }
    for (int t=0; t<nk; t++){
        const int buf = t & 1;
        {   // convert + store prefetched tile
            uint32_t h,l;
            split2(pa0.x,pa0.y,h,l); *(uint32_t*)&Ah[buf][ar][ac+0]=h; *(uint32_t*)&Al[buf][ar][ac+0]=l;
            split2(pa0.z,pa0.w,h,l); *(uint32_t*)&Ah[buf][ar][ac+2]=h; *(uint32_t*)&Al[buf][ar][ac+2]=l;
            split2(pa1.x,pa1.y,h,l); *(uint32_t*)&Ah[buf][ar][ac+4]=h; *(uint32_t*)&Al[buf][ar][ac+4]=l;
            split2(pa1.z,pa1.w,h,l); *(uint32_t*)&Ah[buf][ar][ac+6]=h; *(uint32_t*)&Al[buf][ar][ac+6]=l;
            split2(pb0.x,pb0.y,h,l); *(uint32_t*)&Bh[buf][br][bc+0]=h; *(uint32_t*)&Bl[buf][br][bc+0]=l;
            split2(pb0.z,pb0.w,h,l); *(uint32_t*)&Bh[buf][br][bc+2]=h; *(uint32_t*)&Bl[buf][br][bc+2]=l;
            split2(pb1.x,pb1.y,h,l); *(uint32_t*)&Bh[buf][br][bc+4]=h; *(uint32_t*)&Bl[buf][br][bc+4]=l;
            split2(pb1.z,pb1.w,h,l); *(uint32_t*)&Bh[buf][br][bc+6]=h; *(uint32_t*)&Bl[buf][br][bc+6]=l;
        }
        __syncthreads();
        if (t+1 < nk){
            const float* Ap = Ag + (size_t)ar*K + (t+1)*16 + ac;
            pa0 = *(const float4*)Ap; pa1 = *(const float4*)(Ap+4);
            const float* Bp = Bg + ((size_t)((t+1)*16 + br))*N + bc;
            pb0 = *(const float4*)Bp; pb1 = *(const float4*)(Bp+4);
        }
        // B fragments (hi/lo) for all 4 n-tiles
        uint32_t bh[4][2], bl[4][2];
        #pragma unroll
        for (int nt=0;nt<4;nt++){
            uint32_t ph = (uint32_t)__cvta_generic_to_shared(&Bh[buf][bkrow][wn+nt*8]);
            LDM_X2T(bh[nt][0],bh[nt][1],ph);
            uint32_t pl = (uint32_t)__cvta_generic_to_shared(&Bl[buf][bkrow][wn+nt*8]);
            LDM_X2T(bl[nt][0],bl[nt][1],pl);
        }
        #pragma unroll
        for (int mt=0;mt<4;mt++){
            uint32_t ah0,ah1,ah2,ah3, al0,al1,al2,al3;
            uint32_t pA = (uint32_t)__cvta_generic_to_shared(&Ah[buf][wm+mt*16+arow][acolb]);
            LDM_X4(ah0,ah1,ah2,ah3,pA);
            uint32_t pAl = (uint32_t)__cvta_generic_to_shared(&Al[buf][wm+mt*16+arow][acolb]);
            LDM_X4(al0,al1,al2,al3,pAl);
            #pragma unroll
            for (int nt=0;nt<4;nt++){
                MMA16816(acc[mt][nt], ah0,ah1,ah2,ah3, bh[nt][0],bh[nt][1]);
                MMA16816(acc[mt][nt], ah0,ah1,ah2,ah3, bl[nt][0],bl[nt][1]);
                MMA16816(acc[mt][nt], al0,al1,al2,al3, bh[nt][0],bh[nt][1]);
            }
        }
        __syncthreads();
    }
    // epilogue
    const int g = lane>>2, tq = lane&3;
    #pragma unroll
    for (int nt=0;nt<4;nt++){
        const int col = (int)bx*128 + wn + nt*8 + tq*2;
        float b0=0.f,b1=0.f;
        if (bias){ b0=bias[col]; b1=bias[col+1]; }
        #pragma unroll
        for (int mt=0;mt<4;mt++){
            const int row = (int)by*128 + wm + mt*16 + g;
            float2* p0 = (float2*)(C + (size_t)row*N + col);
            *p0 = make_float2(acc[mt][nt][0]+b0, acc[mt][nt][1]+b1);
            float2* p1 = (float2*)(C + (size_t)(row+8)*N + col);
            *p1 = make_float2(acc[mt][nt][2]+b0, acc[mt][nt][3]+b1);
        }
    }
}

// ---------------- light (windowed) attention ----------------
__global__ __launch_bounds__(64) void k_light(){
    const int w = blockIdx.x, h = blockIdx.y, b = blockIdx.z, t = threadIdx.x;
    __shared__ float ks[WIN][DH];
    __shared__ float vs[WIN][DH];
    const int n0 = w*WIN;
    const float* qp = g_qkv + ((size_t)(b*SEQ + n0 + t))*(3*HDH) + h*DH;
    float q[DH];
    #pragma unroll
    for (int d4=0; d4<DH; d4+=4){
        float4 v = *(const float4*)(qp + d4);
        q[d4]=v.x*0.125f; q[d4+1]=v.y*0.125f; q[d4+2]=v.z*0.125f; q[d4+3]=v.w*0.125f;
    }
    float m=-1e30f, l=0.f, o[DH];
    #pragma unroll
    for (int d=0; d<DH; d++) o[d]=0.f;
    for (int c=0;c<3;c++){
        const int wc = w-1+c;
        if (wc<0 || wc>=NW) continue;
        __syncthreads();
        const float* kb = g_qkv + ((size_t)(b*SEQ + wc*WIN))*(3*HDH) + HDH + h*DH;
        #pragma unroll 4
        for (int i=0;i<WIN;i++){
            ks[i][t] = kb[(size_t)i*(3*HDH) + t];
            vs[i][t] = kb[(size_t)i*(3*HDH) + HDH + t];
        }
        __syncthreads();
        for (int j=0;j<WIN;j++){
            float xv=0.f;
            #pragma unroll
            for (int d=0;d<DH;d++) xv += q[d]*ks[j][d];
            float mn = fmaxf(m, xv);
            float f  = __expf(m-mn);
            float e  = __expf(xv-mn);
            l = l*f + e;
            #pragma unroll
            for (int d=0;d<DH;d++) o[d] = o[d]*f + e*vs[j][d];
            m = mn;
        }
    }
    float inv = 1.f/l;
    float* op = g_lo + ((size_t)(b*SEQ + n0 + t))*HDH + h*DH;
    #pragma unroll
    for (int d4=0; d4<DH; d4+=4){
        float4 v = make_float4(o[d4]*inv, o[d4+1]*inv, o[d4+2]*inv, o[d4+3]*inv);
        *(float4*)(op + d4) = v;
    }
}

// ---------------- coor-descent scalar fixed point ----------------
__global__ __launch_bounds__(1024) void k_coor(){
    const int b = blockIdx.x, r = blockIdx.y;
    const float* s = g_s[r] + (size_t)b*SEQ;
    float sv[8];
    #pragma unroll
    for (int i=0;i<8;i++) sv[i] = s[threadIdx.x + i*1024];
    const double logk = (double)logf(r==0 ? 1152.0f : 2304.0f);
    double a = logk - (double)logf(8192.0f);
    for (int it=0; it<49; it++){
        double tt=0.0;
        #pragma unroll
        for (int i=0;i<8;i++) tt += exp(fmin((double)sv[i], -a));
        tt = blockSumD(tt);
        a = logk - log(tt);
    }
    if (threadIdx.x==0) g_a[r][b] = (float)a;
}

// ---------------- top-k selection ----------------
__global__ __launch_bounds__(1024) void k_select(){
    extern __shared__ unsigned long long keys[];
    const int b = blockIdx.x, r = blockIdx.y;
    const float a = g_a[r][b];
    const float* s = g_s[r] + (size_t)b*SEQ;
    for (int i=threadIdx.x; i<SEQ; i+=1024){
        float sc = expf(fminf(s[i]+a, 0.f));
        unsigned long long key = ((unsigned long long)__float_as_uint(sc)<<32)
                               | (unsigned int)(SEQ-1-i);
        keys[i] = ~key;
    }
    __syncthreads();
    for (int k=2;k<=SEQ;k<<=1){
        for (int j=k>>1;j>0;j>>=1){
            for (int i=threadIdx.x;i<SEQ;i+=1024){
                int ixj = i ^ j;
                if (ixj > i){
                    unsigned long long va = keys[i], vb = keys[ixj];
                    bool sw = ((i & k)==0) ? (va > vb) : (va < vb);
                    if (sw){ keys[i]=vb; keys[ixj]=va; }
                }
            }
            __syncthreads();
        }
    }
    const int cnt = (r==0) ? NQ : NKV;
    for (int i=threadIdx.x;i<cnt;i+=1024){
        unsigned long long key = ~keys[i];
        g_sel[r][b][i] = (SEQ-1) - (int)(key & 0xffffffffu);
    }
}

// ---------------- gather + rmsnorm ----------------
__global__ __launch_bounds__(256) void k_gather(const float* __restrict__ x,
                                                const float* __restrict__ rms_g,
                                                int route){
    const int j = blockIdx.x, b = blockIdx.y;
    const int cnt = route ? NKV : NQ;
    float* out = route ? g_xkvn : g_xqn;
    const int n = g_sel[route][b][j];
    const float* xp = x + ((size_t)(b*SEQ) + n)*DIM;
    float ss=0.f;
    for (int d=threadIdx.x; d<DIM; d+=256){ float v=xp[d]; ss += v*v; }
    ss = blockSum(ss);
    const float sc = 32.f / fmaxf(sqrtf(ss), 1e-12f);
    float* op = out + ((size_t)b*cnt + j)*DIM;
    for (int d=threadIdx.x; d<DIM; d+=256) op[d] = xp[d]*sc*rms_g[d];
}

// ---------------- heavy attention, split-KV partials ----------------
__global__ __launch_bounds__(64) void k_heavy_part(const float* __restrict__ null_kv){
    const int qc = blockIdx.x, h = blockIdx.y;
    const int b  = blockIdx.z >> 2, sp = blockIdx.z & 3;
    const int t  = threadIdx.x;
    __shared__ float ks[64][DH];
    __shared__ float vs[64][DH];
    const int q = qc*64 + t;
    const float* qp = g_qh + ((size_t)(b*NQ + q))*HDH + h*DH;
    float qr[DH];
    #pragma unroll
    for (int d4=0; d4<DH; d4+=4){
        float4 v = *(const float4*)(qp + d4);
        qr[d4]=v.x*0.125f; qr[d4+1]=v.y*0.125f; qr[d4+2]=v.z*0.125f; qr[d4+3]=v.w*0.125f;
    }
    float m, l, o[DH];
    if (sp==0){
        const float* nk = null_kv + h*DH;
        const float* nv = null_kv + HDH + h*DH;
        float x0=0.f;
        #pragma unroll
        for (int d=0;d<DH;d++) x0 += qr[d]*nk[d];
        m=x0; l=1.f;
        #pragma unroll
        for (int d=0;d<DH;d++) o[d]=nv[d];
    } else {
        m=-1e30f; l=0.f;
        #pragma unroll
        for (int d=0;d<DH;d++) o[d]=0.f;
    }
    const int kc0 = sp*(KV_PER_SPLIT/64);
    for (int kc=kc0; kc<kc0 + KV_PER_SPLIT/64; kc++){
        __syncthreads();
        const float* kb = g_kvh + ((size_t)(b*NKV + kc*64))*(2*HDH) + h*(2*DH);
        #pragma unroll 4
        for (int i=0;i<64;i++){
            ks[i][t] = kb[(size_t)i*(2*HDH) + t];
            vs[i][t] = kb[(size_t)i*(2*HDH) + DH + t];
        }
        __syncthreads();
        for (int j=0;j<64;j++){
            float xv=0.f;
            #pragma unroll
            for (int d=0;d<DH;d++) xv += qr[d]*ks[j][d];
            float mn = fmaxf(m, xv);
            float f  = __expf(m-mn);
            float e  = __expf(xv-mn);
            l = l*f + e;
            #pragma unroll
            for (int d=0;d<DH;d++) o[d] = o[d]*f + e*vs[j][d];
            m = mn;
        }
    }
    const size_t base = ((size_t)((b*HEADS+h)*NSPLIT + sp))*NQ + q;
    g_pm[base] = m;
    g_pl[base] = l;
    float* op = g_po + base*DH;
    #pragma unroll
    for (int d4=0; d4<DH; d4+=4)
        *(float4*)(op + d4) = make_float4(o[d4],o[d4+1],o[d4+2],o[d4+3]);
}

// ---------------- combine split-KV partials ----------------
__global__ __launch_bounds__(256) void k_heavy_comb(){
    const int ql = threadIdx.x >> 6, d = threadIdx.x & 63;
    const int q  = blockIdx.x*4 + ql;
    const int h  = blockIdx.y, b = blockIdx.z;
    float m[NSPLIT], l[NSPLIT];
    size_t base[NSPLIT];
    #pragma unroll
    for (int sp=0;sp<NSPLIT;sp++){
        base[sp] = ((size_t)((b*HEADS+h)*NSPLIT + sp))*NQ + q;
        m[sp] = g_pm[base[sp]];
        l[sp] = g_pl[base[sp]];
    }
    float ms = m[0];
    #pragma unroll
    for (int sp=1;sp<NSPLIT;sp++) ms = fmaxf(ms, m[sp]);
    float num=0.f, den=0.f;
    #pragma unroll
    for (int sp=0;sp<NSPLIT;sp++){
        float w = __expf(m[sp]-ms);
        den += l[sp]*w;
        num += g_po[base[sp]*DH + d]*w;
    }
    g_oh[((size_t)(b*NQ)+q)*HDH + h*DH + d] = num/den;
}

// ---------------- scatter routed output ----------------
__global__ __launch_bounds__(256) void k_scatter(const float* __restrict__ null_q,
                                                 float* __restrict__ out){
    const int j=blockIdx.x, b=blockIdx.y;
    const int n = g_sel[0][b][j];
    float* op = out + ((size_t)(b*SEQ) + n)*DIM;
    const float* rp = g_ro + ((size_t)(b*NQ) + j)*DIM;
    for (int d=threadIdx.x; d<DIM; d+=256)
        op[d] += rp[d] - null_q[d];
}

// ---------------- launch ----------------
extern "C" void kernel_launch(void* const* d_in, const int* in_sizes, int n_in,
                              void* d_out, int out_size){
    (void)in_sizes; (void)n_in; (void)out_size;
    const float* x       = (const float*)d_in[0];
    const float* ln_g    = (const float*)d_in[1];
    const float* ln_b    = (const float*)d_in[2];
    const float* w_qkv_l = (const float*)d_in[3];
    const float* w_out_l = (const float*)d_in[4];
    const float* null_q  = (const float*)d_in[5];
    const float* rt_q    = (const float*)d_in[6];
    const float* rt_kv   = (const float*)d_in[7];
    const float* rms_g   = (const float*)d_in[8];
    const float* w_q_h   = (const float*)d_in[9];
    const float* w_kv_h  = (const float*)d_in[10];
    const float* null_kv = (const float*)d_in[11];
    const float* w_out_h = (const float*)d_in[12];
    float* out = (float*)d_out;

    float *p_xn,*p_qkv,*p_lo,*p_xqn,*p_xkvn,*p_qh,*p_kvh,*p_oh,*p_ro;
    cudaGetSymbolAddress((void**)&p_xn,   g_xn);
    cudaGetSymbolAddress((void**)&p_qkv,  g_qkv);
    cudaGetSymbolAddress((void**)&p_lo,   g_lo);
    cudaGetSymbolAddress((void**)&p_xqn,  g_xqn);
    cudaGetSymbolAddress((void**)&p_xkvn, g_xkvn);
    cudaGetSymbolAddress((void**)&p_qh,   g_qh);
    cudaGetSymbolAddress((void**)&p_kvh,  g_kvh);
    cudaGetSymbolAddress((void**)&p_oh,   g_oh);
    cudaGetSymbolAddress((void**)&p_ro,   g_ro);

    cudaFuncSetAttribute(k_select, cudaFuncAttributeMaxDynamicSharedMemorySize, 65536);

    // 1. layernorm + routing logits
    k_pre<<<NROWS, 256>>>(x, ln_g, ln_b, rt_q, rt_kv);
    // 2. light qkv projection (tensor cores)
    gemm_tc<<<dim3(3*HDH/128, NROWS/128), 256>>>(NROWS, 3*HDH, DIM, p_xn, w_qkv_l, p_qkv, nullptr);
    // 3. routing fixed point + selection
    k_coor<<<dim3(BATCH,2), 1024>>>();
    k_select<<<dim3(BATCH,2), 1024, 65536>>>();
    // 4. windowed light attention
    k_light<<<dim3(NW, HEADS, BATCH), 64>>>();
    // 5. light output projection + null_q bias -> d_out
    gemm_tc<<<dim3(DIM/128, NROWS/128), 256>>>(NROWS, DIM, HDH, p_lo, w_out_l, out, null_q);
    // 6. gather + rmsnorm routed tokens
    k_gather<<<dim3(NQ,  BATCH), 256>>>(x, rms_g, 0);
    k_gather<<<dim3(NKV, BATCH), 256>>>(x, rms_g, 1);
    // 7. heavy projections
    gemm_tc<<<dim3(HDH/128,   BATCH*NQ/128),  256>>>(BATCH*NQ,  HDH,   DIM, p_xqn,  w_q_h,  p_qh,  nullptr);
    gemm_tc<<<dim3(2*HDH/128, BATCH*NKV/128), 256>>>(BATCH*NKV, 2*HDH, DIM, p_xkvn, w_kv_h, p_kvh, nullptr);
    // 8. heavy attention: split-KV partials + combine
    k_heavy_part<<<dim3(NQ/64, HEADS, BATCH*NSPLIT), 64>>>(null_kv);
    k_heavy_comb<<<dim3(NQ/4, HEADS, BATCH), 256>>>();
    // 9. heavy output projection
    gemm_tc<<<dim3(DIM/128, BATCH*NQ/128), 256>>>(BATCH*NQ, DIM, HDH, p_oh, w_out_h, p_ro, nullptr);
    // 10. scatter: out[sel] += routed - null_q
    k_scatter<<<dim3(NQ, BATCH), 256>>>(null_q, out);
}

// round 6
// speedup vs baseline: 1.8067x; 1.0521x over previous
#include <cuda_runtime.h>
#include <cuda_bf16.h>
#include <stdint.h>
#include <math.h>

#define BATCH 2
#define SEQ   8192
#define DIM   1024
#define HEADS 8
#define DH    64
#define HDH   512
#define WIN   64
#define NW    (SEQ/WIN)
#define NQ    1024
#define NKV   2048
#define NROWS (BATCH*SEQ)
#define NSPLIT 4
#define KV_PER_SPLIT (NKV/NSPLIT)

// ---------------- scratch ----------------
__device__ float g_xn  [NROWS*DIM];
__device__ float g_qkv [NROWS*3*HDH];
__device__ float g_lo  [NROWS*HDH];
__device__ float g_s   [2][NROWS];
__device__ int   g_sel [2][BATCH][NKV];
__device__ float g_xqn [BATCH*NQ*DIM];
__device__ float g_xkvn[BATCH*NKV*DIM];
__device__ float g_qh  [BATCH*NQ*HDH];
__device__ float g_kvh [BATCH*NKV*2*HDH];
__device__ float g_oh  [BATCH*NQ*HDH];
__device__ float g_ro  [BATCH*NQ*DIM];
__device__ float g_pm  [BATCH*HEADS*NSPLIT*NQ];
__device__ float g_pl  [BATCH*HEADS*NSPLIT*NQ];
__device__ float g_po  [(size_t)BATCH*HEADS*NSPLIT*NQ*DH];

// ---------------- reductions ----------------
__device__ __forceinline__ float blockSum(float v){
    __shared__ float sh[33];
    int lane = threadIdx.x & 31, wid = threadIdx.x >> 5;
    #pragma unroll
    for (int o=16;o>0;o>>=1) v += __shfl_down_sync(0xffffffffu, v, o);
    __syncthreads();
    if (lane==0) sh[wid]=v;
    __syncthreads();
    if (wid==0){
        float r = (lane < (blockDim.x>>5)) ? sh[lane] : 0.f;
        #pragma unroll
        for (int o=16;o>0;o>>=1) r += __shfl_down_sync(0xffffffffu, r, o);
        if (lane==0) sh[32]=r;
    }
    __syncthreads();
    return sh[32];
}

__device__ __forceinline__ double blockSumD(double v){
    __shared__ double shd[33];
    int lane = threadIdx.x & 31, wid = threadIdx.x >> 5;
    #pragma unroll
    for (int o=16;o>0;o>>=1) v += __shfl_down_sync(0xffffffffu, v, o);
    __syncthreads();
    if (lane==0) shd[wid]=v;
    __syncthreads();
    if (wid==0){
        double r = (lane < (blockDim.x>>5)) ? shd[lane] : 0.0;
        #pragma unroll
        for (int o=16;o>0;o>>=1) r += __shfl_down_sync(0xffffffffu, r, o);
        if (lane==0) shd[32]=r;
    }
    __syncthreads();
    return shd[32];
}

// ---------------- fused layernorm + routing logits ----------------
__global__ __launch_bounds__(256) void k_pre(const float* __restrict__ x,
                                             const float* __restrict__ ln_g,
                                             const float* __restrict__ ln_b,
                                             const float* __restrict__ rt_q,
                                             const float* __restrict__ rt_kv){
    __shared__ float xr[DIM];
    size_t row = blockIdx.x;
    const float* xp = x + row*DIM;
    float s=0.f, s2=0.f, dq=0.f, dk=0.f;
    for (int d=threadIdx.x; d<DIM; d+=256){
        float v = xp[d]; xr[d]=v;
        s += v; s2 += v*v; dq += v*rt_q[d]; dk += v*rt_kv[d];
    }
    s  = blockSum(s);
    s2 = blockSum(s2);
    dq = blockSum(dq);
    dk = blockSum(dk);
    if (threadIdx.x==0){ g_s[0][row]=dq; g_s[1][row]=dk; }
    float m    = s * (1.f/DIM);
    float var  = s2 * (1.f/DIM) - m*m;
    float rstd = rsqrtf(var + 1e-5f);
    for (int d=threadIdx.x; d<DIM; d+=256)
        g_xn[row*DIM+d] = (xr[d]-m)*rstd*ln_g[d] + ln_b[d];
}

// ================= tensor-core GEMM (bf16x2 split, fp32-accurate) =========
__device__ __forceinline__ void split2(float x, float y, uint32_t& hi, uint32_t& lo){
    __nv_bfloat16 hx = __float2bfloat16_rn(x), hy = __float2bfloat16_rn(y);
    float rx = x - __bfloat162float(hx);
    float ry = y - __bfloat162float(hy);
    __nv_bfloat16 lx = __float2bfloat16_rn(rx), ly = __float2bfloat16_rn(ry);
    hi = (uint32_t)__bfloat16_as_ushort(hx) | ((uint32_t)__bfloat16_as_ushort(hy)<<16);
    lo = (uint32_t)__bfloat16_as_ushort(lx) | ((uint32_t)__bfloat16_as_ushort(ly)<<16);
}

#define LDM_X4(r0,r1,r2,r3,p) \
    asm volatile("ldmatrix.sync.aligned.m8n8.x4.shared.b16 {%0,%1,%2,%3},[%4];" \
        : "=r"(r0),"=r"(r1),"=r"(r2),"=r"(r3) : "r"(p))
#define LDM_X2T(r0,r1,p) \
    asm volatile("ldmatrix.sync.aligned.m8n8.x2.trans.shared.b16 {%0,%1},[%2];" \
        : "=r"(r0),"=r"(r1) : "r"(p))
#define MMA16816(d,a0,a1,a2,a3,b0,b1) \
    asm volatile("mma.sync.aligned.m16n8k16.row.col.f32.bf16.bf16.f32 " \
        "{%0,%1,%2,%3},{%4,%5,%6,%7},{%8,%9},{%0,%1,%2,%3};" \
        : "+f"(d[0]),"+f"(d[1]),"+f"(d[2]),"+f"(d[3]) \
        : "r"(a0),"r"(a1),"r"(a2),"r"(a3),"r"(b0),"r"(b1))

#define A_LD 24
#define B_LD 136

__global__ __launch_bounds__(256,2) void gemm_tc(int M,int N,int K,
                                                 const float* __restrict__ A,
                                                 const float* __restrict__ B,
                                                 float* __restrict__ C,
                                                 const float* __restrict__ bias){
    __shared__ __nv_bfloat16 Ah[2][128][A_LD];
    __shared__ __nv_bfloat16 Al[2][128][A_LD];
    __shared__ __nv_bfloat16 Bh[2][16][B_LD];
    __shared__ __nv_bfloat16 Bl[2][16][B_LD];
    const int tid  = threadIdx.x;
    const int lane = tid & 31, wid = tid >> 5;
    const int wm = (wid>>2)*64;
    const int wn = (wid&3)*32;
    const size_t bx = blockIdx.x, by = blockIdx.y;
    const float* Ag = A + by*128*(size_t)K;
    const float* Bg = B + bx*128;
    const int ar = tid>>1, ac = (tid&1)*8;
    const int br = tid>>4, bc = (tid&15)*8;
    const int arow  = (lane&7) + ((lane>>3)&1)*8;
    const int acolb = (lane>>4)*8;
    const int bkrow = lane & 15;

    float acc[4][4][4];
    #pragma unroll
    for (int i=0;i<4;i++)
        #pragma unroll
        for (int j=0;j<4;j++)
            #pragma unroll
            for (int c=0;c<4;c++) acc[i][j][c]=0.f;

    const int nk = K >> 4;
    float4 pa0,pa1,pb0,pb1;
    {
        const float* Ap = Ag + (size_t)ar*K + ac;
        pa0 = *(const float4*)Ap; pa1 = *(const float4*)(Ap+4);
        const float* Bp = Bg + (size_t)br*N + bc;
        pb0 = *(const float4*)Bp; pb1 = *(const float4*)(Bp+4);
    }
    for (int t=0; t<nk; t++){
        const int buf = t & 1;
        {
            uint32_t h,l;
            split2(pa0.x,pa0.y,h,l); *(uint32_t*)&Ah[buf][ar][ac+0]=h; *(uint32_t*)&Al[buf][ar][ac+0]=l;
            split2(pa0.z,pa0.w,h,l); *(uint32_t*)&Ah[buf][ar][ac+2]=h; *(uint32_t*)&Al[buf][ar][ac+2]=l;
            split2(pa1.x,pa1.y,h,l); *(uint32_t*)&Ah[buf][ar][ac+4]=h; *(uint32_t*)&Al[buf][ar][ac+4]=l;
            split2(pa1.z,pa1.w,h,l); *(uint32_t*)&Ah[buf][ar][ac+6]=h; *(uint32_t*)&Al[buf][ar][ac+6]=l;
            split2(pb0.x,pb0.y,h,l); *(uint32_t*)&Bh[buf][br][bc+0]=h; *(uint32_t*)&Bl[buf][br][bc+0]=l;
            split2(pb0.z,pb0.w,h,l); *(uint32_t*)&Bh[buf][br][bc+2]=h; *(uint32_t*)&Bl[buf][br][bc+2]=l;
            split2(pb1.x,pb1.y,h,l); *(uint32_t*)&Bh[buf][br][bc+4]=h; *(uint32_t*)&Bl[buf][br][bc+4]=l;
            split2(pb1.z,pb1.w,h,l); *(uint32_t*)&Bh[buf][br][bc+6]=h; *(uint32_t*)&Bl[buf][br][bc+6]=l;
        }
        __syncthreads();
        if (t+1 < nk){
            const float* Ap = Ag + (size_t)ar*K + (t+1)*16 + ac;
            pa0 = *(const float4*)Ap; pa1 = *(const float4*)(Ap+4);
            const float* Bp = Bg + ((size_t)((t+1)*16 + br))*N + bc;
            pb0 = *(const float4*)Bp; pb1 = *(const float4*)(Bp+4);
        }
        uint32_t bhf[4][2], blf[4][2];
        #pragma unroll
        for (int nt=0;nt<4;nt++){
            uint32_t ph = (uint32_t)__cvta_generic_to_shared(&Bh[buf][bkrow][wn+nt*8]);
            LDM_X2T(bhf[nt][0],bhf[nt][1],ph);
            uint32_t pl = (uint32_t)__cvta_generic_to_shared(&Bl[buf][bkrow][wn+nt*8]);
            LDM_X2T(blf[nt][0],blf[nt][1],pl);
        }
        #pragma unroll
        for (int mt=0;mt<4;mt++){
            uint32_t ah0,ah1,ah2,ah3, al0,al1,al2,al3;
            uint32_t pA = (uint32_t)__cvta_generic_to_shared(&Ah[buf][wm+mt*16+arow][acolb]);
            LDM_X4(ah0,ah1,ah2,ah3,pA);
            uint32_t pAl = (uint32_t)__cvta_generic_to_shared(&Al[buf][wm+mt*16+arow][acolb]);
            LDM_X4(al0,al1,al2,al3,pAl);
            #pragma unroll
            for (int nt=0;nt<4;nt++){
                MMA16816(acc[mt][nt], ah0,ah1,ah2,ah3, bhf[nt][0],bhf[nt][1]);
                MMA16816(acc[mt][nt], ah0,ah1,ah2,ah3, blf[nt][0],blf[nt][1]);
                MMA16816(acc[mt][nt], al0,al1,al2,al3, bhf[nt][0],bhf[nt][1]);
            }
        }
        __syncthreads();
    }
    const int g = lane>>2, tq = lane&3;
    #pragma unroll
    for (int nt=0;nt<4;nt++){
        const int col = (int)bx*128 + wn + nt*8 + tq*2;
        float b0=0.f,b1=0.f;
        if (bias){ b0=bias[col]; b1=bias[col+1]; }
        #pragma unroll
        for (int mt=0;mt<4;mt++){
            const int row = (int)by*128 + wm + mt*16 + g;
            float2* p0 = (float2*)(C + (size_t)row*N + col);
            *p0 = make_float2(acc[mt][nt][0]+b0, acc[mt][nt][1]+b1);
            float2* p1 = (float2*)(C + (size_t)(row+8)*N + col);
            *p1 = make_float2(acc[mt][nt][2]+b0, acc[mt][nt][3]+b1);
        }
    }
}

// ---------------- light (windowed) attention (float4 smem, 4-way ILP) -----
__global__ __launch_bounds__(64) void k_light(){
    const int w = blockIdx.x, h = blockIdx.y, b = blockIdx.z, t = threadIdx.x;
    __shared__ float4 ks4[WIN][16];
    __shared__ float4 vs4[WIN][16];
    const int n0 = w*WIN;
    const float* qp = g_qkv + ((size_t)(b*SEQ + n0 + t))*(3*HDH) + h*DH;
    float4 q4[16];
    #pragma unroll
    for (int c=0;c<16;c++){
        float4 v = *(const float4*)(qp + c*4);
        q4[c] = make_float4(v.x*0.125f, v.y*0.125f, v.z*0.125f, v.w*0.125f);
    }
    float m=-1e30f, l=0.f;
    float4 o4[16];
    #pragma unroll
    for (int c=0;c<16;c++) o4[c]=make_float4(0.f,0.f,0.f,0.f);
    for (int c=0;c<3;c++){
        const int wc = w-1+c;
        if (wc<0 || wc>=NW) continue;
        __syncthreads();
        const float* kb = g_qkv + ((size_t)(b*SEQ + wc*WIN))*(3*HDH) + HDH + h*DH;
        #pragma unroll 4
        for (int i=0;i<WIN;i++){
            ((float*)&ks4[i][0])[t] = kb[(size_t)i*(3*HDH) + t];
            ((float*)&vs4[i][0])[t] = kb[(size_t)i*(3*HDH) + HDH + t];
        }
        __syncthreads();
        for (int j=0;j<WIN;j++){
            float x0=0.f,x1=0.f,x2=0.f,x3=0.f;
            #pragma unroll
            for (int cc=0;cc<16;cc++){
                float4 k4 = ks4[j][cc];
                x0 += q4[cc].x*k4.x; x1 += q4[cc].y*k4.y;
                x2 += q4[cc].z*k4.z; x3 += q4[cc].w*k4.w;
            }
            float xv = (x0+x1)+(x2+x3);
            float mn = fmaxf(m, xv);
            float f  = __expf(m-mn);
            float e  = __expf(xv-mn);
            l = l*f + e;
            #pragma unroll
            for (int cc=0;cc<16;cc++){
                float4 v4 = vs4[j][cc];
                o4[cc].x = o4[cc].x*f + e*v4.x;
                o4[cc].y = o4[cc].y*f + e*v4.y;
                o4[cc].z = o4[cc].z*f + e*v4.z;
                o4[cc].w = o4[cc].w*f + e*v4.w;
            }
            m = mn;
        }
    }
    float inv = 1.f/l;
    float* op = g_lo + ((size_t)(b*SEQ + n0 + t))*HDH + h*DH;
    #pragma unroll
    for (int cc=0;cc<16;cc++)
        *(float4*)(op + cc*4) = make_float4(o4[cc].x*inv, o4[cc].y*inv,
                                            o4[cc].z*inv, o4[cc].w*inv);
}

// ---------------- routing: fixed point + radix top-k set selection --------
// One block per (b, route). a via exp-hoisted fixed point (E=exp(s) once),
// then selection set = top-cnt under (score desc, idx asc) via radix select
// on f32 score bits + index-ordered ranks among threshold ties.
__global__ __launch_bounds__(1024) void k_route(){
    const int b = blockIdx.x, r = blockIdx.y;
    const int tid = threadIdx.x;
    const int cnt = (r==0) ? NQ : NKV;
    const float* s = g_s[r] + (size_t)b*SEQ;
    // per-thread 8 contiguous tokens (index order preserved for tie ranks)
    float sv[8];
    {
        float4 v0 = *(const float4*)(s + tid*8);
        float4 v1 = *(const float4*)(s + tid*8 + 4);
        sv[0]=v0.x; sv[1]=v0.y; sv[2]=v0.z; sv[3]=v0.w;
        sv[4]=v1.x; sv[5]=v1.y; sv[6]=v1.z; sv[7]=v1.w;
    }
    double E[8];
    #pragma unroll
    for (int i=0;i<8;i++) E[i] = exp((double)sv[i]);
    __shared__ double aSh;
    const double logk = (double)logf(r==0 ? 1152.0f : 2304.0f);
    double a = logk - (double)logf(8192.0f);   // iteration 1
    for (int it=0; it<49; it++){               // iterations 2..50
        double T = exp(-a);
        double tt=0.0;
        #pragma unroll
        for (int i=0;i<8;i++) tt += fmin(E[i], T);
        tt = blockSumD(tt);
        if (tid==0) aSh = logk - log(tt);
        __syncthreads();
        a = aSh;
        __syncthreads();
    }
    const float af = (float)a;
    // f32 scores (same expression as reference path)
    uint32_t u[8];
    #pragma unroll
    for (int i=0;i<8;i++)
        u[i] = __float_as_uint(expf(fminf(sv[i]+af, 0.f)));
    // radix select: cnt-th largest score value (with multiplicity)
    __shared__ int hist[256];
    __shared__ uint32_t pbc; __shared__ int rbc;
    uint32_t prefix = 0; int remaining = cnt;
    for (int shift=24; shift>=0; shift-=8){
        for (int cc=tid; cc<256; cc+=1024) hist[cc]=0;
        __syncthreads();
        uint32_t pmask = (shift==24) ? 0u : (0xFFFFFFFFu << (shift+8));
        #pragma unroll
        for (int i=0;i<8;i++)
            if ((u[i] & pmask) == prefix)
                atomicAdd(&hist[(u[i]>>shift)&255], 1);
        __syncthreads();
        if (tid==0){
            int rem = remaining; uint32_t dig = 0;
            for (int d=255; d>=0; d--){
                int hv = hist[d];
                if (rem - hv <= 0){ dig = (uint32_t)d; break; }
                rem -= hv;
            }
            pbc = prefix | (dig<<shift);
            rbc = rem;
        }
        __syncthreads();
        prefix = pbc; remaining = rbc;
        __syncthreads();
    }
    const uint32_t ut = prefix;              // threshold score bits
    const int Cgt = cnt - remaining;         // # strictly above threshold
    // ranks: (count >ut) any order; (count ==ut) in index order
    __shared__ int sgt[1024], seqv[1024];
    int cgt=0, ceq=0;
    #pragma unroll
    for (int i=0;i<8;i++){
        if (u[i] > ut) cgt++;
        else if (u[i] == ut) ceq++;
    }
    sgt[tid]=cgt; seqv[tid]=ceq;
    __syncthreads();
    for (int off=1; off<1024; off<<=1){
        int a0=0,b0=0;
        if (tid>=off){ a0=sgt[tid-off]; b0=seqv[tid-off]; }
        __syncthreads();
        sgt[tid]+=a0; seqv[tid]+=b0;
        __syncthreads();
    }
    int gtPos = sgt[tid]-cgt;
    int eqPos = seqv[tid]-ceq;
    #pragma unroll
    for (int i=0;i<8;i++){
        const int idx = tid*8 + i;
        if (u[i] > ut){
            g_sel[r][b][gtPos++] = idx;
        } else if (u[i] == ut){
            int rk = eqPos++;
            if (rk < remaining) g_sel[r][b][Cgt + rk] = idx;
        }
    }
}

// ---------------- gather + rmsnorm ----------------
__global__ __launch_bounds__(256) void k_gather(const float* __restrict__ x,
                                                const float* __restrict__ rms_g,
                                                int route){
    const int j = blockIdx.x, b = blockIdx.y;
    const int cnt = route ? NKV : NQ;
    float* out = route ? g_xkvn : g_xqn;
    const int n = g_sel[route][b][j];
    const float* xp = x + ((size_t)(b*SEQ) + n)*DIM;
    float ss=0.f;
    for (int d=threadIdx.x; d<DIM; d+=256){ float v=xp[d]; ss += v*v; }
    ss = blockSum(ss);
    const float sc = 32.f / fmaxf(sqrtf(ss), 1e-12f);
    float* op = out + ((size_t)b*cnt + j)*DIM;
    for (int d=threadIdx.x; d<DIM; d+=256) op[d] = xp[d]*sc*rms_g[d];
}

// ---------------- heavy attention, split-KV partials (float4/ILP) ---------
__global__ __launch_bounds__(64) void k_heavy_part(const float* __restrict__ null_kv){
    const int qc = blockIdx.x, h = blockIdx.y;
    const int b  = blockIdx.z >> 2, sp = blockIdx.z & 3;
    const int t  = threadIdx.x;
    __shared__ float4 ks4[64][16];
    __shared__ float4 vs4[64][16];
    const int q = qc*64 + t;
    const float* qp = g_qh + ((size_t)(b*NQ + q))*HDH + h*DH;
    float4 q4[16];
    #pragma unroll
    for (int c=0;c<16;c++){
        float4 v = *(const float4*)(qp + c*4);
        q4[c] = make_float4(v.x*0.125f, v.y*0.125f, v.z*0.125f, v.w*0.125f);
    }
    float m, l;
    float4 o4[16];
    if (sp==0){
        const float* nk = null_kv + h*DH;
        const float* nv = null_kv + HDH + h*DH;
        float x0=0.f;
        #pragma unroll
        for (int c=0;c<16;c++){
            x0 += q4[c].x*nk[c*4] + q4[c].y*nk[c*4+1]
                + q4[c].z*nk[c*4+2] + q4[c].w*nk[c*4+3];
        }
        m=x0; l=1.f;
        #pragma unroll
        for (int c=0;c<16;c++)
            o4[c]=make_float4(nv[c*4],nv[c*4+1],nv[c*4+2],nv[c*4+3]);
    } else {
        m=-1e30f; l=0.f;
        #pragma unroll
        for (int c=0;c<16;c++) o4[c]=make_float4(0.f,0.f,0.f,0.f);
    }
    const int kc0 = sp*(KV_PER_SPLIT/64);
    for (int kc=kc0; kc<kc0 + KV_PER_SPLIT/64; kc++){
        __syncthreads();
        const float* kb = g_kvh + ((size_t)(b*NKV + kc*64))*(2*HDH) + h*(2*DH);
        #pragma unroll 4
        for (int i=0;i<64;i++){
            ((float*)&ks4[i][0])[t] = kb[(size_t)i*(2*HDH) + t];
            ((float*)&vs4[i][0])[t] = kb[(size_t)i*(2*HDH) + DH + t];
        }
        __syncthreads();
        for (int j=0;j<64;j++){
            float x0=0.f,x1=0.f,x2=0.f,x3=0.f;
            #pragma unroll
            for (int cc=0;cc<16;cc++){
                float4 k4 = ks4[j][cc];
                x0 += q4[cc].x*k4.x; x1 += q4[cc].y*k4.y;
                x2 += q4[cc].z*k4.z; x3 += q4[cc].w*k4.w;
            }
            float xv = (x0+x1)+(x2+x3);
            float mn = fmaxf(m, xv);
            float f  = __expf(m-mn);
            float e  = __expf(xv-mn);
            l = l*f + e;
            #pragma unroll
            for (int cc=0;cc<16;cc++){
                float4 v4 = vs4[j][cc];
                o4[cc].x = o4[cc].x*f + e*v4.x;
                o4[cc].y = o4[cc].y*f + e*v4.y;
                o4[cc].z = o4[cc].z*f + e*v4.z;
                o4[cc].w = o4[cc].w*f + e*v4.w;
            }
            m = mn;
        }
    }
    const size_t base = ((size_t)((b*HEADS+h)*NSPLIT + sp))*NQ + q;
    g_pm[base] = m;
    g_pl[base] = l;
    float* op = g_po + base*DH;
    #pragma unroll
    for (int cc=0;cc<16;cc++)
        *(float4*)(op + cc*4) = o4[cc];
}

// ---------------- combine split-KV partials ----------------
__global__ __launch_bounds__(256) void k_heavy_comb(){
    const int ql = threadIdx.x >> 6, d = threadIdx.x & 63;
    const int q  = blockIdx.x*4 + ql;
    const int h  = blockIdx.y, b = blockIdx.z;
    float m[NSPLIT], l[NSPLIT];
    size_t base[NSPLIT];
    #pragma unroll
    for (int sp=0;sp<NSPLIT;sp++){
        base[sp] = ((size_t)((b*HEADS+h)*NSPLIT + sp))*NQ + q;
        m[sp] = g_pm[base[sp]];
        l[sp] = g_pl[base[sp]];
    }
    float ms = m[0];
    #pragma unroll
    for (int sp=1;sp<NSPLIT;sp++) ms = fmaxf(ms, m[sp]);
    float num=0.f, den=0.f;
    #pragma unroll
    for (int sp=0;sp<NSPLIT;sp++){
        float w = __expf(m[sp]-ms);
        den += l[sp]*w;
        num += g_po[base[sp]*DH + d]*w;
    }
    g_oh[((size_t)(b*NQ)+q)*HDH + h*DH + d] = num/den;
}

// ---------------- scatter routed output ----------------
__global__ __launch_bounds__(256) void k_scatter(const float* __restrict__ null_q,
                                                 float* __restrict__ out){
    const int j=blockIdx.x, b=blockIdx.y;
    const int n = g_sel[0][b][j];
    float* op = out + ((size_t)(b*SEQ) + n)*DIM;
    const float* rp = g_ro + ((size_t)(b*NQ) + j)*DIM;
    for (int d=threadIdx.x; d<DIM; d+=256)
        op[d] += rp[d] - null_q[d];
}

// ---------------- launch ----------------
extern "C" void kernel_launch(void* const* d_in, const int* in_sizes, int n_in,
                              void* d_out, int out_size){
    (void)in_sizes; (void)n_in; (void)out_size;
    const float* x       = (const float*)d_in[0];
    const float* ln_g    = (const float*)d_in[1];
    const float* ln_b    = (const float*)d_in[2];
    const float* w_qkv_l = (const float*)d_in[3];
    const float* w_out_l = (const float*)d_in[4];
    const float* null_q  = (const float*)d_in[5];
    const float* rt_q    = (const float*)d_in[6];
    const float* rt_kv   = (const float*)d_in[7];
    const float* rms_g   = (const float*)d_in[8];
    const float* w_q_h   = (const float*)d_in[9];
    const float* w_kv_h  = (const float*)d_in[10];
    const float* null_kv = (const float*)d_in[11];
    const float* w_out_h = (const float*)d_in[12];
    float* out = (float*)d_out;

    float *p_xn,*p_qkv,*p_lo,*p_xqn,*p_xkvn,*p_qh,*p_kvh,*p_oh,*p_ro;
    cudaGetSymbolAddress((void**)&p_xn,   g_xn);
    cudaGetSymbolAddress((void**)&p_qkv,  g_qkv);
    cudaGetSymbolAddress((void**)&p_lo,   g_lo);
    cudaGetSymbolAddress((void**)&p_xqn,  g_xqn);
    cudaGetSymbolAddress((void**)&p_xkvn, g_xkvn);
    cudaGetSymbolAddress((void**)&p_qh,   g_qh);
    cudaGetSymbolAddress((void**)&p_kvh,  g_kvh);
    cudaGetSymbolAddress((void**)&p_oh,   g_oh);
    cudaGetSymbolAddress((void**)&p_ro,   g_ro);

    // 1. layernorm + routing logits
    k_pre<<<NROWS, 256>>>(x, ln_g, ln_b, rt_q, rt_kv);
    // 2. light qkv projection (tensor cores)
    gemm_tc<<<dim3(3*HDH/128, NROWS/128), 256>>>(NROWS, 3*HDH, DIM, p_xn, w_qkv_l, p_qkv, nullptr);
    // 3. routing: fixed point + top-k set selection (one kernel)
    k_route<<<dim3(BATCH,2), 1024>>>();
    // 4. windowed light attention
    k_light<<<dim3(NW, HEADS, BATCH), 64>>>();
    // 5. light output projection + null_q bias -> d_out
    gemm_tc<<<dim3(DIM/128, NROWS/128), 256>>>(NROWS, DIM, HDH, p_lo, w_out_l, out, null_q);
    // 6. gather + rmsnorm routed tokens
    k_gather<<<dim3(NQ,  BATCH), 256>>>(x, rms_g, 0);
    k_gather<<<dim3(NKV, BATCH), 256>>>(x, rms_g, 1);
    // 7. heavy projections
    gemm_tc<<<dim3(HDH/128,   BATCH*NQ/128),  256>>>(BATCH*NQ,  HDH,   DIM, p_xqn,  w_q_h,  p_qh,  nullptr);
    gemm_tc<<<dim3(2*HDH/128, BATCH*NKV/128), 256>>>(BATCH*NKV, 2*HDH, DIM, p_xkvn, w_kv_h, p_kvh, nullptr);
    // 8. heavy attention: split-KV partials + combine
    k_heavy_part<<<dim3(NQ/64, HEADS, BATCH*NSPLIT), 64>>>(null_kv);
    k_heavy_comb<<<dim3(NQ/4, HEADS, BATCH), 256>>>();
    // 9. heavy output projection
    gemm_tc<<<dim3(DIM/128, BATCH*NQ/128), 256>>>(BATCH*NQ, DIM, HDH, p_oh, w_out_h, p_ro, nullptr);
    // 10. scatter: out[sel] += routed - null_q
    k_scatter<<<dim3(NQ, BATCH), 256>>>(null_q, out);
}